// round 4
// baseline (speedup 1.0000x reference)
#include <cuda_runtime.h>
#include <math.h>

#define BB   16
#define NN   2048
#define DD   128
#define NSL  8
#define HH   128
#define RWS  (BB*NSL)            // 128 slot rows
#define EPSV 1e-8f
#define PSTR 132

// ---------------- scratch (__device__ globals: allocation-free) ----------------
__device__ float g_k[BB*NN*DD];          // 16 MB, k == v
__device__ float g_mus[RWS*DD];          // mu_s (GRU hidden)
__device__ float g_qmu[RWS*DD];
__device__ float g_inv[RWS*DD];
__device__ float g_pi[RWS];
__device__ float g_gsum[RWS];
__device__ float g_accV[RWS*DD];
__device__ float g_accV2[RWS*DD];

// transposed weights
__device__ float g_WkT[DD*DD];           // [kk][c]
__device__ float g_WqT[DD*DD];           // [c][d]
__device__ float g_WihT[DD*3*DD];        // [c][j]
__device__ float g_WhhT[DD*3*DD];
__device__ float g_W1muT[DD*HH];         // [c][j]
__device__ float g_W2muT[HH*DD];         // [j][d]
__device__ float g_W1oT[2*DD*2*HH];      // [c][j]
__device__ float g_W2oT[2*HH*DD];        // [c][d]

// ---------------- kT: one-time weight transposes ----------------
__global__ void kT(const float* __restrict__ Wk, const float* __restrict__ Wq,
                   const float* __restrict__ Wih, const float* __restrict__ Whh,
                   const float* __restrict__ W1mu, const float* __restrict__ W2mu,
                   const float* __restrict__ W1o, const float* __restrict__ W2o) {
  int tid = blockIdx.x*blockDim.x + threadIdx.x;
  int stride = gridDim.x*blockDim.x;
  for (int i=tid;i<DD*DD;i+=stride){int c=i>>7,kk=i&127; g_WkT[kk*DD+c]=Wk[i];}
  for (int i=tid;i<DD*DD;i+=stride){int d=i>>7,c=i&127;  g_WqT[c*DD+d]=Wq[i];}
  for (int i=tid;i<3*DD*DD;i+=stride){int j=i>>7,c=i&127; g_WihT[c*384+j]=Wih[i]; g_WhhT[c*384+j]=Whh[i];}
  for (int i=tid;i<HH*DD;i+=stride){int j=i>>7,c=i&127;  g_W1muT[c*HH+j]=W1mu[i];}
  for (int i=tid;i<DD*HH;i+=stride){int d=i>>7,j=i&127;  g_W2muT[j*DD+d]=W2mu[i];}
  for (int i=tid;i<2*HH*2*DD;i+=stride){int j=i>>8,c=i&255; g_W1oT[c*256+j]=W1o[i];}
  for (int i=tid;i<DD*2*HH;i+=stride){int d=i>>8,c=i&255; g_W2oT[c*DD+d]=W2o[i];}
}

// ---------------- kA: fused LayerNorm + k = xn @ Wk^T ----------------
__global__ void kA(const float* __restrict__ inp,
                   const float* __restrict__ lng, const float* __restrict__ lnb) {
  __shared__ float xs[64*DD];
  __shared__ float wt[16*DD];
  const int tid = threadIdx.x;
  const int r0blk = blockIdx.x*64;
  for (int idx=tid; idx<64*DD; idx+=256) xs[idx] = inp[(long)r0blk*DD + idx];
  __syncthreads();
  { // LayerNorm: warp w -> rows w*8..w*8+7
    int w = tid>>5, lane = tid&31;
    for (int r=w*8; r<w*8+8; ++r) {
      float x0=xs[r*DD+lane],    x1=xs[r*DD+lane+32];
      float x2=xs[r*DD+lane+64], x3=xs[r*DD+lane+96];
      float s = x0+x1+x2+x3;
      #pragma unroll
      for (int o=16;o;o>>=1) s += __shfl_xor_sync(0xffffffffu,s,o);
      float m = s*(1.f/128.f);
      float d0=x0-m,d1=x1-m,d2=x2-m,d3=x3-m;
      float s2 = d0*d0+d1*d1+d2*d2+d3*d3;
      #pragma unroll
      for (int o=16;o;o>>=1) s2 += __shfl_xor_sync(0xffffffffu,s2,o);
      float rs = rsqrtf(s2*(1.f/128.f)+1e-5f);
      xs[r*DD+lane]    = d0*rs*lng[lane]    + lnb[lane];
      xs[r*DD+lane+32] = d1*rs*lng[lane+32] + lnb[lane+32];
      xs[r*DD+lane+64] = d2*rs*lng[lane+64] + lnb[lane+64];
      xs[r*DD+lane+96] = d3*rs*lng[lane+96] + lnb[lane+96];
    }
  }
  const int cg = tid&31, rg = tid>>5;
  const int c0 = cg*4, r0 = rg*8;
  float4 acc[8];
  #pragma unroll
  for (int r=0;r<8;++r) acc[r] = make_float4(0.f,0.f,0.f,0.f);
  for (int kt=0; kt<8; ++kt) {
    __syncthreads();
    for (int i=tid; i<16*DD; i+=256) wt[i] = g_WkT[kt*16*DD + i];
    __syncthreads();
    #pragma unroll 4
    for (int kk=0;kk<16;++kk) {
      float4 wv = *(const float4*)&wt[kk*DD+c0];
      int kg = kt*16 + kk;
      #pragma unroll
      for (int r=0;r<8;++r) {
        float xv = xs[(r0+r)*DD+kg];
        acc[r].x = fmaf(xv,wv.x,acc[r].x);
        acc[r].y = fmaf(xv,wv.y,acc[r].y);
        acc[r].z = fmaf(xv,wv.z,acc[r].z);
        acc[r].w = fmaf(xv,wv.w,acc[r].w);
      }
    }
  }
  #pragma unroll
  for (int r=0;r<8;++r)
    *(float4*)&g_k[(long)(r0blk + r0 + r)*DD + c0] = acc[r];
}

// ---------------- qphase4: LN(slots)+Wq for 4 rows, 256 threads ----------------
__device__ __forceinline__ void qphase4(int r0, float (*sv)[256], float (*sn)[256],
                                        float* red,
                                        const float* __restrict__ lsg,
                                        const float* __restrict__ lsb, int t) {
  int q = t>>6, tl = t&63, lane = t&31, w = t>>5;
  float v0=sv[q][tl], v1=sv[q][tl+64], v2=sv[q][tl+128], v3=sv[q][tl+192];
  float s = v0+v1+v2+v3;
  #pragma unroll
  for (int o=16;o;o>>=1) s += __shfl_xor_sync(0xffffffffu,s,o);
  if (lane==0) red[w] = s;
  __syncthreads();
  float m = (red[q*2]+red[q*2+1])*(1.f/256.f);
  __syncthreads();
  float d0=v0-m,d1=v1-m,d2=v2-m,d3=v3-m;
  float s2 = d0*d0+d1*d1+d2*d2+d3*d3;
  #pragma unroll
  for (int o=16;o;o>>=1) s2 += __shfl_xor_sync(0xffffffffu,s2,o);
  if (lane==0) red[w] = s2;
  __syncthreads();
  float rs = rsqrtf((red[q*2]+red[q*2+1])*(1.f/256.f) + 1e-5f);
  sn[q][tl]     = d0*rs*lsg[tl]     + lsb[tl];
  sn[q][tl+64]  = d1*rs*lsg[tl+64]  + lsb[tl+64];
  sn[q][tl+128] = d2*rs*lsg[tl+128] + lsb[tl+128];
  sn[q][tl+192] = d3*rs*lsg[tl+192] + lsb[tl+192];
  __syncthreads();
  int tt = t&127, th = t>>7;
  float acc[4] = {0,0,0,0};
  int base = th*128;
  #pragma unroll 4
  for (int c=0;c<128;++c) {
    float wv = g_WqT[c*DD+tt];
    #pragma unroll
    for (int q2=0;q2<4;++q2) acc[q2] = fmaf(sn[q2][base+c], wv, acc[q2]);
  }
  if (th==0) {
    #pragma unroll
    for (int q2=0;q2<4;++q2) {
      g_qmu[(r0+q2)*DD+tt] = acc[q2];
      g_mus[(r0+q2)*DD+tt] = sn[q2][tt];
      g_accV[(r0+q2)*DD+tt] = 0.f;
      g_accV2[(r0+q2)*DD+tt] = 0.f;
    }
  } else {
    #pragma unroll
    for (int q2=0;q2<4;++q2) g_inv[(r0+q2)*DD+tt] = expf(-2.f*acc[q2]);
  }
  if (t<4) g_gsum[r0+t] = 0.f;
}

// ---------------- kInit: slot init + pi + first Q-phase (4 rows/block) ----------
__global__ void kInit(const float* __restrict__ noise, const float* __restrict__ smu,
                      const float* __restrict__ slsig,
                      const float* __restrict__ lsg, const float* __restrict__ lsb) {
  __shared__ float sv[4][256];
  __shared__ float sn[4][256];
  __shared__ float red[8];
  int r0 = blockIdx.x*4, t = threadIdx.x;
  for (int i=t; i<1024; i+=256) {
    int q = i>>8, d = i&255;
    sv[q][d] = smu[d] + expf(slsig[d])*noise[(r0+q)*256+d];
  }
  if (t<4) g_pi[r0+t] = 1.f/(float)NSL;
  __syncthreads();
  qphase4(r0, sv, sn, red, lsg, lsb, t);
}

// ---------------- kP: fused dots/gamma/moment pass (float4 vectorized) ----------
__global__ void kP() {
  __shared__ float ks[32*PSTR];
  __shared__ float qm[8*PSTR];
  __shared__ float iv[8*PSTR];
  __shared__ float gam[8*36];
  __shared__ float spi[8];
  __shared__ float sgs[8];
  int b = blockIdx.x, chunk = blockIdx.y;
  int tid = threadIdx.x, lane = tid&31, w = tid>>5;
  { // load qm/iv: 8 slots x 32 float4
    int s = tid>>5, d4 = tid&31;
    ((float4*)&qm[s*PSTR])[d4] = ((const float4*)&g_qmu[(b*8+s)*DD])[d4];
    ((float4*)&iv[s*PSTR])[d4] = ((const float4*)&g_inv[(b*8+s)*DD])[d4];
  }
  if (tid<8) { spi[tid] = g_pi[b*8+tid]; sgs[tid] = 0.f; }
  int slot = lane&7, rloc = lane>>3;
  float4 accV = make_float4(0,0,0,0), acc2 = make_float4(0,0,0,0);
  float gpart = 0.f;
  long kbase = (long)b*NN*DD + (long)chunk*128*DD;
  for (int tile=0; tile<4; ++tile) {
    __syncthreads();
    { // load 32 rows x 32 float4
      const float4* src = (const float4*)&g_k[kbase + tile*32*DD];
      for (int i=tid; i<1024; i+=256) {
        int rr = i>>5, c4 = i&31;
        ((float4*)&ks[rr*PSTR])[c4] = src[rr*32 + c4];
      }
    }
    __syncthreads();
    { // gamma: warp w -> rows w*4..w*4+3; lane -> (row=w*4+rloc, slot)
      int row = w*4 + rloc;
      const float4* kr = (const float4*)&ks[row*PSTR];
      const float4* qs = (const float4*)&qm[slot*PSTR];
      const float4* is = (const float4*)&iv[slot*PSTR];
      float dx=0.f, dy=0.f, dz=0.f, dw=0.f;
      #pragma unroll 8
      for (int i=0; i<32; ++i) {
        float4 k4 = kr[i], q4 = qs[i], i4 = is[i];
        float a = k4.x-q4.x, bb = k4.y-q4.y, c = k4.z-q4.z, d = k4.w-q4.w;
        dx = fmaf(i4.x*a,  a,  dx);
        dy = fmaf(i4.y*bb, bb, dy);
        dz = fmaf(i4.z*c,  c,  dz);
        dw = fmaf(i4.w*d,  d,  dw);
      }
      float dot = (dx+dy)+(dz+dw);
      float e = (expf(-dot) + EPSV) * spi[slot];
      float ssum = e;
      ssum += __shfl_xor_sync(0xffffffffu, ssum, 1);
      ssum += __shfl_xor_sync(0xffffffffu, ssum, 2);
      ssum += __shfl_xor_sync(0xffffffffu, ssum, 4);
      float g = e / ssum;
      gam[slot*36 + row] = g;
      gpart += g;
    }
    __syncthreads();
    { // accum: warp w == slot w; lane covers d = lane*4..lane*4+3
      const float* gr = &gam[w*36];
      #pragma unroll 4
      for (int n=0; n<32; ++n) {
        float g = gr[n];
        float4 k4 = ((const float4*)&ks[n*PSTR])[lane];
        float t0=g*k4.x, t1=g*k4.y, t2=g*k4.z, t3=g*k4.w;
        accV.x += t0; accV.y += t1; accV.z += t2; accV.w += t3;
        acc2.x = fmaf(t0,k4.x,acc2.x); acc2.y = fmaf(t1,k4.y,acc2.y);
        acc2.z = fmaf(t2,k4.z,acc2.z); acc2.w = fmaf(t3,k4.w,acc2.w);
      }
    }
  }
  gpart += __shfl_xor_sync(0xffffffffu, gpart, 8);
  gpart += __shfl_xor_sync(0xffffffffu, gpart, 16);
  if (lane<8) atomicAdd(&sgs[slot], gpart);
  int r = b*8 + w, d0 = lane*4;
  atomicAdd(&g_accV [r*DD+d0+0], accV.x);
  atomicAdd(&g_accV [r*DD+d0+1], accV.y);
  atomicAdd(&g_accV [r*DD+d0+2], accV.z);
  atomicAdd(&g_accV [r*DD+d0+3], accV.w);
  atomicAdd(&g_accV2[r*DD+d0+0], acc2.x);
  atomicAdd(&g_accV2[r*DD+d0+1], acc2.y);
  atomicAdd(&g_accV2[r*DD+d0+2], acc2.z);
  atomicAdd(&g_accV2[r*DD+d0+3], acc2.w);
  __syncthreads();
  if (tid<8) atomicAdd(&g_gsum[b*8+tid], sgs[tid]);
}

// ---------------- kUQ: GRU+LN+MLP+logsigma then Q-phase/final, 4 rows/block ----
__global__ void kUQ(const float* __restrict__ bih, const float* __restrict__ bhh,
                    const float* __restrict__ b1, const float* __restrict__ b2,
                    const float* __restrict__ lmg, const float* __restrict__ lmb,
                    const float* __restrict__ lsg, const float* __restrict__ lsb,
                    const float* __restrict__ b1o, const float* __restrict__ b2o,
                    float* __restrict__ outp, int last) {
  __shared__ float s1s[4][128], s2s[4][128], mus[4][128], ups[4][128];
  __shared__ float ps[6][4][256];
  __shared__ float hs[4][128], m1[4][128];
  __shared__ float sv[4][256], sn[4][256];
  __shared__ float red[8];
  __shared__ float gsums[4];
  int r0 = blockIdx.x*4, t = threadIdx.x, tt = t&127, th = t>>7;
  if (t<4) gsums[t] = g_gsum[r0+t];
  __syncthreads();
  for (int i=t; i<512; i+=256) {
    int q = i>>7, d = i&127;
    float inv = 1.f/gsums[q];
    s1s[q][d] = g_accV [(r0+q)*DD+d]*inv;
    s2s[q][d] = g_accV2[(r0+q)*DD+d]*inv;
    mus[q][d] = g_mus  [(r0+q)*DD+d];
  }
  __syncthreads();
  { // GRU gate partials: c-half th, 6 gates x 4 rows
    float a[24];
    #pragma unroll
    for (int i=0;i<24;++i) a[i]=0.f;
    int c0 = th*64;
    for (int c=c0; c<c0+64; ++c) {
      const float* wi = &g_WihT[c*384];
      const float* wh = &g_WhhT[c*384];
      float wir=wi[tt], wiz=wi[128+tt], win=wi[256+tt];
      float whr=wh[tt], whz=wh[128+tt], whn=wh[256+tt];
      #pragma unroll
      for (int q=0;q<4;++q) {
        float xv = s1s[q][c], hv = mus[q][c];
        a[q]    = fmaf(xv,wir,a[q]);
        a[4+q]  = fmaf(xv,wiz,a[4+q]);
        a[8+q]  = fmaf(xv,win,a[8+q]);
        a[12+q] = fmaf(hv,whr,a[12+q]);
        a[16+q] = fmaf(hv,whz,a[16+q]);
        a[20+q] = fmaf(hv,whn,a[20+q]);
      }
    }
    #pragma unroll
    for (int g=0;g<6;++g)
      #pragma unroll
      for (int q=0;q<4;++q) ps[g][q][t] = a[g*4+q];
  }
  __syncthreads();
  #pragma unroll
  for (int rep=0; rep<2; ++rep) { // gates+GRU output: 2 (q,j) per thread
    int q = th*2 + rep, j = tt;
    float Gir = ps[0][q][j]+ps[0][q][j+128] + bih[j];
    float Giz = ps[1][q][j]+ps[1][q][j+128] + bih[128+j];
    float Gin = ps[2][q][j]+ps[2][q][j+128] + bih[256+j];
    float Ghr = ps[3][q][j]+ps[3][q][j+128] + bhh[j];
    float Ghz = ps[4][q][j]+ps[4][q][j+128] + bhh[128+j];
    float Ghn = ps[5][q][j]+ps[5][q][j+128] + bhh[256+j];
    float rg = 1.f/(1.f+expf(-(Gir+Ghr)));
    float zg = 1.f/(1.f+expf(-(Giz+Ghz)));
    float ng = tanhf(Gin + rg*Ghn);
    ups[q][j] = (1.f-zg)*ng + zg*mus[q][j];
  }
  __syncthreads();
  { // LN(ups) per row: 64 threads/row
    int q = t>>6, tl = t&63, lane = t&31, w = t>>5;
    float v0 = ups[q][tl], v1 = ups[q][tl+64];
    float s = v0+v1;
    #pragma unroll
    for (int o=16;o;o>>=1) s += __shfl_xor_sync(0xffffffffu,s,o);
    if (lane==0) red[w] = s;
    __syncthreads();
    float m = (red[q*2]+red[q*2+1])*(1.f/128.f);
    __syncthreads();
    float d0 = v0-m, d1 = v1-m;
    float s2 = d0*d0+d1*d1;
    #pragma unroll
    for (int o=16;o;o>>=1) s2 += __shfl_xor_sync(0xffffffffu,s2,o);
    if (lane==0) red[w] = s2;
    __syncthreads();
    float rs = rsqrtf((red[q*2]+red[q*2+1])*(1.f/128.f) + 1e-5f);
    hs[q][tl]    = d0*rs*lmg[tl]    + lmb[tl];
    hs[q][tl+64] = d1*rs*lmg[tl+64] + lmb[tl+64];
  }
  __syncthreads();
  { // MLP1 partials
    float a1[4] = {0,0,0,0};
    int c0 = th*64;
    #pragma unroll 4
    for (int c=c0; c<c0+64; ++c) {
      float wv = g_W1muT[c*HH+tt];
      #pragma unroll
      for (int q=0;q<4;++q) a1[q] = fmaf(hs[q][c], wv, a1[q]);
    }
    #pragma unroll
    for (int q=0;q<4;++q) ps[0][q][t] = a1[q];
  }
  __syncthreads();
  #pragma unroll
  for (int rep=0; rep<2; ++rep) {
    int q = th*2 + rep;
    m1[q][tt] = fmaxf(ps[0][q][tt]+ps[0][q][tt+128]+b1[tt], 0.f);
  }
  __syncthreads();
  { // MLP2 partials
    float a2[4] = {0,0,0,0};
    int j0 = th*64;
    #pragma unroll 4
    for (int j=j0; j<j0+64; ++j) {
      float wv = g_W2muT[j*DD+tt];
      #pragma unroll
      for (int q=0;q<4;++q) a2[q] = fmaf(m1[q][j], wv, a2[q]);
    }
    #pragma unroll
    for (int q=0;q<4;++q) ps[1][q][t] = a2[q];
  }
  __syncthreads();
  #pragma unroll
  for (int rep=0; rep<2; ++rep) {
    int q = th*2 + rep;
    float out = ups[q][tt] + b2[tt] + ps[1][q][tt] + ps[1][q][tt+128];
    float ls = 0.5f*logf(s2s[q][tt] - 2.f*out*s1s[q][tt] + out*out + EPSV);
    sv[q][tt]     = out;
    sv[q][128+tt] = ls;
  }
  if (t<4) g_pi[r0+t] = gsums[t];
  __syncthreads();
  if (!last) {
    qphase4(r0, sv, sn, red, lsg, lsb, t);
  } else {
    { // h = relu(sv @ W1o^T + b1o): output t, 4 rows
      float a[4] = {0,0,0,0};
      #pragma unroll 4
      for (int c=0;c<256;++c) {
        float wv = g_W1oT[c*256+t];
        #pragma unroll
        for (int q=0;q<4;++q) a[q] = fmaf(sv[q][c], wv, a[q]);
      }
      #pragma unroll
      for (int q=0;q<4;++q) sn[q][t] = fmaxf(a[q]+b1o[t], 0.f);
    }
    __syncthreads();
    { // out = sn @ W2o^T + b2o: c-half split
      float o[4] = {0,0,0,0};
      int cc0 = th*128;
      #pragma unroll 4
      for (int c=cc0; c<cc0+128; ++c) {
        float wv = g_W2oT[c*DD+tt];
        #pragma unroll
        for (int q=0;q<4;++q) o[q] = fmaf(sn[q][c], wv, o[q]);
      }
      #pragma unroll
      for (int q=0;q<4;++q) ps[2][q][t] = o[q];
    }
    __syncthreads();
    #pragma unroll
    for (int rep=0; rep<2; ++rep) {
      int q = th*2 + rep;
      outp[(r0+q)*DD+tt] = ps[2][q][tt] + ps[2][q][tt+128] + b2o[tt];
    }
  }
}

extern "C" void kernel_launch(void* const* d_in, const int* in_sizes, int n_in,
                              void* d_out, int out_size) {
  const float* inputs  = (const float*)d_in[0];
  const float* noise   = (const float*)d_in[1];
  const float* smu     = (const float*)d_in[2];
  const float* slsig   = (const float*)d_in[3];
  const float* Wq      = (const float*)d_in[4];
  const float* Wk      = (const float*)d_in[5];
  const float* Wih     = (const float*)d_in[6];
  const float* Whh     = (const float*)d_in[7];
  const float* bih     = (const float*)d_in[8];
  const float* bhh     = (const float*)d_in[9];
  const float* W1mu    = (const float*)d_in[10];
  const float* b1mu    = (const float*)d_in[11];
  const float* W2mu    = (const float*)d_in[12];
  const float* b2mu    = (const float*)d_in[13];
  const float* ln_in_g = (const float*)d_in[14];
  const float* ln_in_b = (const float*)d_in[15];
  const float* lsg     = (const float*)d_in[16];
  const float* lsb     = (const float*)d_in[17];
  const float* lmg     = (const float*)d_in[18];
  const float* lmb     = (const float*)d_in[19];
  const float* W1o     = (const float*)d_in[20];
  const float* b1o     = (const float*)d_in[21];
  const float* W2o     = (const float*)d_in[22];
  const float* b2o     = (const float*)d_in[23];
  float* out = (float*)d_out;

  kT<<<64, 256>>>(Wk, Wq, Wih, Whh, W1mu, W2mu, W1o, W2o);
  kA<<<(BB*NN)/64, 256>>>(inputs, ln_in_g, ln_in_b);
  kInit<<<RWS/4, 256>>>(noise, smu, slsig, lsg, lsb);
  for (int it=0; it<4; ++it) {
    kP<<<dim3(BB, NN/128), 256>>>();
    kUQ<<<RWS/4, 256>>>(bih, bhh, b1mu, b2mu, lmg, lmb, lsg, lsb,
                        b1o, b2o, out, it==3 ? 1 : 0);
  }
}

// round 5
// speedup vs baseline: 1.0041x; 1.0041x over previous
#include <cuda_runtime.h>
#include <math.h>

#define BB   16
#define NN   2048
#define DD   128
#define NSL  8
#define HH   128
#define RWS  (BB*NSL)            // 128 slot rows
#define EPSV 1e-8f
#define PSTR 132
#define CH   64                  // n-rows per kP chunk

// ---------------- scratch (__device__ globals: allocation-free) ----------------
__device__ float g_k[BB*NN*DD];          // 16 MB, k == v
__device__ float g_mus[RWS*DD];          // mu_s (GRU hidden)
__device__ float g_wa[RWS*DD];           // inv_var
__device__ float g_wb[RWS*DD];           // -2*inv*qmu
__device__ float g_wc[RWS];              // sum inv*qmu^2
__device__ float g_pi[RWS];
__device__ float g_gsum[RWS];
__device__ float g_accV[RWS*DD];
__device__ float g_accV2[RWS*DD];

// transposed weights
__device__ float g_WkT[DD*DD];           // [kk][c]
__device__ float g_WqT[DD*DD];           // [c][d]
__device__ float g_WihT[DD*3*DD];        // [c][j]
__device__ float g_WhhT[DD*3*DD];
__device__ float g_W1muT[DD*HH];         // [c][j]
__device__ float g_W2muT[HH*DD];         // [j][d]
__device__ float g_W1oT[2*DD*2*HH];      // [c][j]
__device__ float g_W2oT[2*HH*DD];        // [c][d]

// ---------------- kT: one-time weight transposes ----------------
__global__ void kT(const float* __restrict__ Wk, const float* __restrict__ Wq,
                   const float* __restrict__ Wih, const float* __restrict__ Whh,
                   const float* __restrict__ W1mu, const float* __restrict__ W2mu,
                   const float* __restrict__ W1o, const float* __restrict__ W2o) {
  int tid = blockIdx.x*blockDim.x + threadIdx.x;
  int stride = gridDim.x*blockDim.x;
  for (int i=tid;i<DD*DD;i+=stride){int c=i>>7,kk=i&127; g_WkT[kk*DD+c]=Wk[i];}
  for (int i=tid;i<DD*DD;i+=stride){int d=i>>7,c=i&127;  g_WqT[c*DD+d]=Wq[i];}
  for (int i=tid;i<3*DD*DD;i+=stride){int j=i>>7,c=i&127; g_WihT[c*384+j]=Wih[i]; g_WhhT[c*384+j]=Whh[i];}
  for (int i=tid;i<HH*DD;i+=stride){int j=i>>7,c=i&127;  g_W1muT[c*HH+j]=W1mu[i];}
  for (int i=tid;i<DD*HH;i+=stride){int d=i>>7,j=i&127;  g_W2muT[j*DD+d]=W2mu[i];}
  for (int i=tid;i<2*HH*2*DD;i+=stride){int j=i>>8,c=i&255; g_W1oT[c*256+j]=W1o[i];}
  for (int i=tid;i<DD*2*HH;i+=stride){int d=i>>8,c=i&255; g_W2oT[c*DD+d]=W2o[i];}
}

// ---------------- kA: fused LayerNorm + k = xn @ Wk^T ----------------
__global__ void kA(const float* __restrict__ inp,
                   const float* __restrict__ lng, const float* __restrict__ lnb) {
  __shared__ float xs[64*DD];
  __shared__ float wt[16*DD];
  const int tid = threadIdx.x;
  const int r0blk = blockIdx.x*64;
  for (int idx=tid; idx<64*DD; idx+=256) xs[idx] = inp[(long)r0blk*DD + idx];
  __syncthreads();
  { // LayerNorm: warp w -> rows w*8..w*8+7
    int w = tid>>5, lane = tid&31;
    for (int r=w*8; r<w*8+8; ++r) {
      float x0=xs[r*DD+lane],    x1=xs[r*DD+lane+32];
      float x2=xs[r*DD+lane+64], x3=xs[r*DD+lane+96];
      float s = x0+x1+x2+x3;
      #pragma unroll
      for (int o=16;o;o>>=1) s += __shfl_xor_sync(0xffffffffu,s,o);
      float m = s*(1.f/128.f);
      float d0=x0-m,d1=x1-m,d2=x2-m,d3=x3-m;
      float s2 = d0*d0+d1*d1+d2*d2+d3*d3;
      #pragma unroll
      for (int o=16;o;o>>=1) s2 += __shfl_xor_sync(0xffffffffu,s2,o);
      float rs = rsqrtf(s2*(1.f/128.f)+1e-5f);
      xs[r*DD+lane]    = d0*rs*lng[lane]    + lnb[lane];
      xs[r*DD+lane+32] = d1*rs*lng[lane+32] + lnb[lane+32];
      xs[r*DD+lane+64] = d2*rs*lng[lane+64] + lnb[lane+64];
      xs[r*DD+lane+96] = d3*rs*lng[lane+96] + lnb[lane+96];
    }
  }
  const int cg = tid&31, rg = tid>>5;
  const int c0 = cg*4, r0 = rg*8;
  float4 acc[8];
  #pragma unroll
  for (int r=0;r<8;++r) acc[r] = make_float4(0.f,0.f,0.f,0.f);
  for (int kt=0; kt<8; ++kt) {
    __syncthreads();
    for (int i=tid; i<16*DD; i+=256) wt[i] = g_WkT[kt*16*DD + i];
    __syncthreads();
    #pragma unroll 4
    for (int kk=0;kk<16;++kk) {
      float4 wv = *(const float4*)&wt[kk*DD+c0];
      int kg = kt*16 + kk;
      #pragma unroll
      for (int r=0;r<8;++r) {
        float xv = xs[(r0+r)*DD+kg];
        acc[r].x = fmaf(xv,wv.x,acc[r].x);
        acc[r].y = fmaf(xv,wv.y,acc[r].y);
        acc[r].z = fmaf(xv,wv.z,acc[r].z);
        acc[r].w = fmaf(xv,wv.w,acc[r].w);
      }
    }
  }
  #pragma unroll
  for (int r=0;r<8;++r)
    *(float4*)&g_k[(long)(r0blk + r0 + r)*DD + c0] = acc[r];
}

// ---------------- 8-warp block reduce ----------------
__device__ __forceinline__ float blkSum8(float v, float* red, int tid) {
  int lane = tid&31, w = tid>>5;
  #pragma unroll
  for (int o=16;o;o>>=1) v += __shfl_xor_sync(0xffffffffu,v,o);
  if (lane==0) red[w] = v;
  __syncthreads();
  float tot = red[0]+red[1]+red[2]+red[3]+red[4]+red[5]+red[6]+red[7];
  __syncthreads();
  return tot;
}

// ---------------- Q-phase: LN(slots) + Wq -> wa/wb/wc, 256 threads, 1 row ------
__device__ __forceinline__ void qphase(int r, const float* sv, float* sn,
                                       float* tmp, float* red,
                                       const float* __restrict__ lsg,
                                       const float* __restrict__ lsb, int t) {
  float x = sv[t];
  float m = blkSum8(x, red, t) * (1.f/256.f);
  float dv = x - m;
  float var = blkSum8(dv*dv, red, t) * (1.f/256.f);
  float rs = rsqrtf(var + 1e-5f);
  sn[t] = dv*rs*lsg[t] + lsb[t];
  __syncthreads();
  int idx = t & 127;
  const float* s = (t < 128) ? &sn[0] : &sn[128];
  float acc = 0.f;
  #pragma unroll 8
  for (int c=0;c<128;++c) acc = fmaf(s[c], g_WqT[c*DD+idx], acc);
  if (t >= 128) {
    float inv = expf(-2.f*acc);
    g_wa[r*DD+idx] = inv;
    tmp[idx] = inv;
  }
  __syncthreads();
  float cpart = 0.f;
  if (t < 128) {
    float inv = tmp[t];
    g_wb[r*DD+t] = -2.f*inv*acc;     // acc == qmu here
    g_mus[r*DD+t] = sn[t];
    g_accV[r*DD+t] = 0.f;
    g_accV2[r*DD+t] = 0.f;
    cpart = inv*acc*acc;
  }
  float C = blkSum8(cpart, red, t);
  if (t==0) { g_wc[r] = C; g_gsum[r] = 0.f; }
}

// ---------------- kInit: slot init + pi + first Q-phase ----------------
__global__ void kInit(const float* __restrict__ noise, const float* __restrict__ smu,
                      const float* __restrict__ slsig,
                      const float* __restrict__ lsg, const float* __restrict__ lsb) {
  __shared__ float sv[256];
  __shared__ float sn[256];
  __shared__ float tmp[128];
  __shared__ float red[8];
  int r = blockIdx.x, t = threadIdx.x;
  sv[t] = smu[t] + expf(slsig[t])*noise[r*256+t];
  if (t==0) g_pi[r] = 1.f/(float)NSL;
  __syncthreads();
  qphase(r, sv, sn, tmp, red, lsg, lsb, t);
}

// ---------------- kP: fused dots/gamma/moment pass (register wa/wb) ------------
// grid (16 b, 32 chunks of 64 n), 256 threads
__global__ void kP() {
  __shared__ float ks[CH*PSTR];        // 33.8 KB
  __shared__ float gm[CH*8];           // gammas [n][slot]
  __shared__ float sA[8*DD];           // accV staging
  __shared__ float sB[8*DD];           // acc2 staging
  __shared__ float sgs[8];
  int b = blockIdx.x, chunk = blockIdx.y;
  int tid = threadIdx.x, lane = tid&31, w = tid>>5;
  for (int i=tid; i<8*DD; i+=256) { sA[i]=0.f; sB[i]=0.f; }
  if (tid<8) sgs[tid]=0.f;
  // per-thread slot vectors in registers: lane -> d-chunk lane*4..lane*4+3
  float4 wa[8], wb[8];
  #pragma unroll
  for (int s=0;s<8;++s) {
    wa[s] = ((const float4*)&g_wa[(b*8+s)*DD])[lane];
    wb[s] = ((const float4*)&g_wb[(b*8+s)*DD])[lane];
  }
  float Cs  = g_wc[b*8 + (lane&7)];
  float pis = g_pi[b*8 + (lane&7)];
  { // load tile: 64 rows x 32 float4
    const float4* src = (const float4*)&g_k[(long)b*NN*DD + (long)chunk*CH*DD];
    for (int i=tid; i<CH*32; i+=256) {
      int rr = i>>5, c4 = i&31;
      ((float4*)&ks[rr*PSTR])[c4] = src[i];
    }
  }
  __syncthreads();
  // phase 1 (dots/gammas): warp w -> rows w*8..w*8+7
  float gpart = 0.f;
  #pragma unroll 1
  for (int ni=0; ni<8; ++ni) {
    int n = w*8 + ni;
    float4 k4 = ((const float4*)&ks[n*PSTR])[lane];
    float part[8];
    #pragma unroll
    for (int s=0;s<8;++s) {
      float m0 = fmaf(wa[s].x, k4.x, wb[s].x);
      float m1 = fmaf(wa[s].y, k4.y, wb[s].y);
      float m2 = fmaf(wa[s].z, k4.z, wb[s].z);
      float m3 = fmaf(wa[s].w, k4.w, wb[s].w);
      float p = m0*k4.x;
      p = fmaf(m1, k4.y, p);
      p = fmaf(m2, k4.z, p);
      p = fmaf(m3, k4.w, p);
      part[s] = p;
    }
    float myDot = 0.f;
    #pragma unroll
    for (int s=0;s<8;++s) {
      float v = part[s];
      v += __shfl_xor_sync(0xffffffffu, v, 16);
      v += __shfl_xor_sync(0xffffffffu, v, 8);
      v += __shfl_xor_sync(0xffffffffu, v, 4);
      v += __shfl_xor_sync(0xffffffffu, v, 2);
      v += __shfl_xor_sync(0xffffffffu, v, 1);
      if ((lane&7)==s) myDot = v;
    }
    float e = (expf(-(myDot + Cs)) + EPSV) * pis;
    float ssum = e;
    ssum += __shfl_xor_sync(0xffffffffu, ssum, 1);
    ssum += __shfl_xor_sync(0xffffffffu, ssum, 2);
    ssum += __shfl_xor_sync(0xffffffffu, ssum, 4);
    float g = e / ssum;
    if (lane<8) { gm[n*8+lane] = g; gpart += g; }
  }
  if (lane<8) atomicAdd(&sgs[lane], gpart);
  __syncthreads();
  // phase 2 (moments): warp w -> n-quarter (w>>1), slot-half (w&1)
  {
    int nq = w>>1, sh = w&1;
    float4 aV[4], a2[4];
    #pragma unroll
    for (int j=0;j<4;++j) { aV[j]=make_float4(0,0,0,0); a2[j]=make_float4(0,0,0,0); }
    #pragma unroll 2
    for (int ni=0; ni<16; ++ni) {
      int n = nq*16 + ni;
      float4 k4 = ((const float4*)&ks[n*PSTR])[lane];
      float4 g4 = ((const float4*)&gm[n*8])[sh];
      float gj[4] = {g4.x, g4.y, g4.z, g4.w};
      #pragma unroll
      for (int j=0;j<4;++j) {
        float t0=gj[j]*k4.x, t1=gj[j]*k4.y, t2=gj[j]*k4.z, t3=gj[j]*k4.w;
        aV[j].x += t0; aV[j].y += t1; aV[j].z += t2; aV[j].w += t3;
        a2[j].x = fmaf(t0,k4.x,a2[j].x); a2[j].y = fmaf(t1,k4.y,a2[j].y);
        a2[j].z = fmaf(t2,k4.z,a2[j].z); a2[j].w = fmaf(t3,k4.w,a2[j].w);
      }
    }
    int d0 = lane*4;
    #pragma unroll
    for (int j=0;j<4;++j) {
      int s = sh*4 + j;
      atomicAdd(&sA[s*DD+d0+0], aV[j].x); atomicAdd(&sA[s*DD+d0+1], aV[j].y);
      atomicAdd(&sA[s*DD+d0+2], aV[j].z); atomicAdd(&sA[s*DD+d0+3], aV[j].w);
      atomicAdd(&sB[s*DD+d0+0], a2[j].x); atomicAdd(&sB[s*DD+d0+1], a2[j].y);
      atomicAdd(&sB[s*DD+d0+2], a2[j].z); atomicAdd(&sB[s*DD+d0+3], a2[j].w);
    }
  }
  __syncthreads();
  for (int i=tid; i<8*DD; i+=256) {
    atomicAdd(&g_accV [b*8*DD + i], sA[i]);
    atomicAdd(&g_accV2[b*8*DD + i], sB[i]);
  }
  if (tid<8) atomicAdd(&g_gsum[b*8+tid], sgs[tid]);
}

// ---------------- kUQ: GRU + LN + MLP + logsigma, then Q-phase (or final MLP) ----
// 128 blocks (slot rows), 256 threads; contraction dims split across thread halves
__global__ void kUQ(const float* __restrict__ bih, const float* __restrict__ bhh,
                    const float* __restrict__ b1, const float* __restrict__ b2,
                    const float* __restrict__ lmg, const float* __restrict__ lmb,
                    const float* __restrict__ lsg, const float* __restrict__ lsb,
                    const float* __restrict__ b1o, const float* __restrict__ b2o,
                    float* __restrict__ outp, int last) {
  __shared__ float s1s[128], s2s[128], mus[128];
  __shared__ float ps[6*256];
  __shared__ float hs[128];
  __shared__ float m1[128];
  __shared__ float sv[256];
  __shared__ float sn[256];
  __shared__ float tmp[128];
  __shared__ float red[8];
  int r = blockIdx.x, t = threadIdx.x, tt = t & 127, th = t >> 7;
  float gsum = g_gsum[r];
  if (t < 128) {
    float inv = 1.f/gsum;
    s1s[t] = g_accV[r*DD+t]*inv;
    s2s[t] = g_accV2[r*DD+t]*inv;
    mus[t] = g_mus[r*DD+t];
  }
  __syncthreads();
  // GRU gates: thread (th,tt) covers c in [th*64, th*64+64)
  {
    float gir=0,giz=0,gin=0,ghr=0,ghz=0,ghn=0;
    int c0 = th*64;
    #pragma unroll 8
    for (int c=c0; c<c0+64; ++c) {
      float xv = s1s[c], hv = mus[c];
      const float* wi = &g_WihT[c*384];
      const float* wh = &g_WhhT[c*384];
      gir = fmaf(xv, wi[tt],     gir);  ghr = fmaf(hv, wh[tt],     ghr);
      giz = fmaf(xv, wi[128+tt], giz);  ghz = fmaf(hv, wh[128+tt], ghz);
      gin = fmaf(xv, wi[256+tt], gin);  ghn = fmaf(hv, wh[256+tt], ghn);
    }
    ps[t]=gir; ps[256+t]=giz; ps[512+t]=gin;
    ps[768+t]=ghr; ps[1024+t]=ghz; ps[1280+t]=ghn;
  }
  __syncthreads();
  float upd1 = 0.f;
  if (t < 128) {
    float Gir = ps[t]+ps[t+128]       + bih[t];
    float Giz = ps[256+t]+ps[384+t]   + bih[128+t];
    float Gin = ps[512+t]+ps[640+t]   + bih[256+t];
    float Ghr = ps[768+t]+ps[896+t]   + bhh[t];
    float Ghz = ps[1024+t]+ps[1152+t] + bhh[128+t];
    float Ghn = ps[1280+t]+ps[1408+t] + bhh[256+t];
    float rg = 1.f/(1.f+expf(-(Gir+Ghr)));
    float zg = 1.f/(1.f+expf(-(Giz+Ghz)));
    float ng = tanhf(Gin + rg*Ghn);
    upd1 = (1.f-zg)*ng + zg*mus[t];
  }
  __syncthreads();
  // LN(upd1) over 128 (inactive threads contribute 0)
  {
    float v = (t<128) ? upd1 : 0.f;
    float m = blkSum8(v, red, t) * (1.f/128.f);
    float dv = (t<128) ? (upd1 - m) : 0.f;
    float var = blkSum8(dv*dv, red, t) * (1.f/128.f);
    float rs = rsqrtf(var + 1e-5f);
    if (t<128) hs[t] = dv*rs*lmg[t] + lmb[t];
  }
  __syncthreads();
  // MLP1: split c over halves
  {
    float a = 0.f;
    int c0 = th*64;
    #pragma unroll 8
    for (int c=c0; c<c0+64; ++c) a = fmaf(hs[c], g_W1muT[c*HH+tt], a);
    ps[t] = a;
  }
  __syncthreads();
  if (t < 128) m1[t] = fmaxf(ps[t]+ps[t+128]+b1[t], 0.f);
  __syncthreads();
  // MLP2: split j over halves
  {
    float a = 0.f;
    int j0 = th*64;
    #pragma unroll 8
    for (int j=j0; j<j0+64; ++j) a = fmaf(m1[j], g_W2muT[j*DD+tt], a);
    ps[t] = a;
  }
  __syncthreads();
  if (t < 128) {
    float out = upd1 + b2[t] + ps[t] + ps[t+128];
    float ls = 0.5f*logf(s2s[t] - 2.f*out*s1s[t] + out*out + EPSV);
    sv[t] = out;
    sv[128+t] = ls;
    if (t==0) g_pi[r] = gsum;
  }
  __syncthreads();
  if (!last) {
    qphase(r, sv, sn, tmp, red, lsg, lsb, t);
  } else {
    // final output MLP: h = relu(sv @ W1o^T + b1o), out = h @ W2o^T + b2o
    float a = b1o[t];
    #pragma unroll 8
    for (int c=0;c<256;++c) a = fmaf(sv[c], g_W1oT[c*256+t], a);
    sn[t] = fmaxf(a, 0.f);
    __syncthreads();
    if (t < 128) {
      float o = b2o[t];
      #pragma unroll 8
      for (int c=0;c<256;++c) o = fmaf(sn[c], g_W2oT[c*DD+t], o);
      outp[r*DD+t] = o;
    }
  }
}

extern "C" void kernel_launch(void* const* d_in, const int* in_sizes, int n_in,
                              void* d_out, int out_size) {
  const float* inputs  = (const float*)d_in[0];
  const float* noise   = (const float*)d_in[1];
  const float* smu     = (const float*)d_in[2];
  const float* slsig   = (const float*)d_in[3];
  const float* Wq      = (const float*)d_in[4];
  const float* Wk      = (const float*)d_in[5];
  const float* Wih     = (const float*)d_in[6];
  const float* Whh     = (const float*)d_in[7];
  const float* bih     = (const float*)d_in[8];
  const float* bhh     = (const float*)d_in[9];
  const float* W1mu    = (const float*)d_in[10];
  const float* b1mu    = (const float*)d_in[11];
  const float* W2mu    = (const float*)d_in[12];
  const float* b2mu    = (const float*)d_in[13];
  const float* ln_in_g = (const float*)d_in[14];
  const float* ln_in_b = (const float*)d_in[15];
  const float* lsg     = (const float*)d_in[16];
  const float* lsb     = (const float*)d_in[17];
  const float* lmg     = (const float*)d_in[18];
  const float* lmb     = (const float*)d_in[19];
  const float* W1o     = (const float*)d_in[20];
  const float* b1o     = (const float*)d_in[21];
  const float* W2o     = (const float*)d_in[22];
  const float* b2o     = (const float*)d_in[23];
  float* out = (float*)d_out;

  kT<<<64, 256>>>(Wk, Wq, Wih, Whh, W1mu, W2mu, W1o, W2o);
  kA<<<(BB*NN)/64, 256>>>(inputs, ln_in_g, ln_in_b);
  kInit<<<RWS, 256>>>(noise, smu, slsig, lsg, lsb);
  for (int it=0; it<4; ++it) {
    kP<<<dim3(BB, NN/CH), 256>>>();
    kUQ<<<RWS, 256>>>(bih, bhh, b1mu, b2mu, lmg, lmb, lsg, lsb,
                      b1o, b2o, out, it==3 ? 1 : 0);
  }
}

// round 7
// speedup vs baseline: 1.1998x; 1.1950x over previous
#include <cuda_runtime.h>
#include <math.h>

#define BB   16
#define NN   2048
#define DD   128
#define NSL  8
#define HH   128
#define RWS  (BB*NSL)            // 128 slot rows
#define EPSV 1e-8f
#define CH   64                  // n-rows per kP chunk
#define KSTR 33                  // float4 stride for ks rows

// ---------------- scratch (__device__ globals: allocation-free) ----------------
__device__ float g_k[BB*NN*DD];          // 16 MB, k == v
__device__ float g_mus[RWS*DD];          // mu_s (GRU hidden)
__device__ float g_wa[RWS*DD];           // inv_var
__device__ float g_wb[RWS*DD];           // -2*inv*qmu
__device__ float g_wc[RWS];              // sum inv*qmu^2
__device__ float g_pi[RWS];
__device__ float g_gsum[RWS];
__device__ float g_accV[RWS*DD];
__device__ float g_accV2[RWS*DD];

// transposed weights
__device__ float g_WkT[DD*DD];           // [kk][c]
__device__ float g_WqT[DD*DD];           // [c][d]
__device__ float g_WihT[DD*3*DD];        // [c][j]
__device__ float g_WhhT[DD*3*DD];
__device__ float g_W1muT[DD*HH];         // [c][j]
__device__ float g_W2muT[HH*DD];         // [j][d]
__device__ float g_W1oT[2*DD*2*HH];      // [c][j]
__device__ float g_W2oT[2*HH*DD];        // [c][d]

// ---------------- kT: one-time weight transposes ----------------
__global__ void kT(const float* __restrict__ Wk, const float* __restrict__ Wq,
                   const float* __restrict__ Wih, const float* __restrict__ Whh,
                   const float* __restrict__ W1mu, const float* __restrict__ W2mu,
                   const float* __restrict__ W1o, const float* __restrict__ W2o) {
  int tid = blockIdx.x*blockDim.x + threadIdx.x;
  int stride = gridDim.x*blockDim.x;
  for (int i=tid;i<DD*DD;i+=stride){int c=i>>7,kk=i&127; g_WkT[kk*DD+c]=Wk[i];}
  for (int i=tid;i<DD*DD;i+=stride){int d=i>>7,c=i&127;  g_WqT[c*DD+d]=Wq[i];}
  for (int i=tid;i<3*DD*DD;i+=stride){int j=i>>7,c=i&127; g_WihT[c*384+j]=Wih[i]; g_WhhT[c*384+j]=Whh[i];}
  for (int i=tid;i<HH*DD;i+=stride){int j=i>>7,c=i&127;  g_W1muT[c*HH+j]=W1mu[i];}
  for (int i=tid;i<DD*HH;i+=stride){int d=i>>7,j=i&127;  g_W2muT[j*DD+d]=W2mu[i];}
  for (int i=tid;i<2*HH*2*DD;i+=stride){int j=i>>8,c=i&255; g_W1oT[c*256+j]=W1o[i];}
  for (int i=tid;i<DD*2*HH;i+=stride){int d=i>>8,c=i&255; g_W2oT[c*DD+d]=W2o[i];}
}

// ---------------- kA: fused LayerNorm + k = xn @ Wk^T ----------------
__global__ void kA(const float* __restrict__ inp,
                   const float* __restrict__ lng, const float* __restrict__ lnb) {
  __shared__ float xs[64*DD];
  __shared__ float wt[16*DD];
  const int tid = threadIdx.x;
  const int r0blk = blockIdx.x*64;
  for (int idx=tid; idx<64*DD; idx+=256) xs[idx] = inp[(long)r0blk*DD + idx];
  __syncthreads();
  { // LayerNorm: warp w -> rows w*8..w*8+7
    int w = tid>>5, lane = tid&31;
    for (int r=w*8; r<w*8+8; ++r) {
      float x0=xs[r*DD+lane],    x1=xs[r*DD+lane+32];
      float x2=xs[r*DD+lane+64], x3=xs[r*DD+lane+96];
      float s = x0+x1+x2+x3;
      #pragma unroll
      for (int o=16;o;o>>=1) s += __shfl_xor_sync(0xffffffffu,s,o);
      float m = s*(1.f/128.f);
      float d0=x0-m,d1=x1-m,d2=x2-m,d3=x3-m;
      float s2 = d0*d0+d1*d1+d2*d2+d3*d3;
      #pragma unroll
      for (int o=16;o;o>>=1) s2 += __shfl_xor_sync(0xffffffffu,s2,o);
      float rs = rsqrtf(s2*(1.f/128.f)+1e-5f);
      xs[r*DD+lane]    = d0*rs*lng[lane]    + lnb[lane];
      xs[r*DD+lane+32] = d1*rs*lng[lane+32] + lnb[lane+32];
      xs[r*DD+lane+64] = d2*rs*lng[lane+64] + lnb[lane+64];
      xs[r*DD+lane+96] = d3*rs*lng[lane+96] + lnb[lane+96];
    }
  }
  const int cg = tid&31, rg = tid>>5;
  const int c0 = cg*4, r0 = rg*8;
  float4 acc[8];
  #pragma unroll
  for (int r=0;r<8;++r) acc[r] = make_float4(0.f,0.f,0.f,0.f);
  for (int kt=0; kt<8; ++kt) {
    __syncthreads();
    for (int i=tid; i<16*DD; i+=256) wt[i] = g_WkT[kt*16*DD + i];
    __syncthreads();
    #pragma unroll 4
    for (int kk=0;kk<16;++kk) {
      float4 wv = *(const float4*)&wt[kk*DD+c0];
      int kg = kt*16 + kk;
      #pragma unroll
      for (int r=0;r<8;++r) {
        float xv = xs[(r0+r)*DD+kg];
        acc[r].x = fmaf(xv,wv.x,acc[r].x);
        acc[r].y = fmaf(xv,wv.y,acc[r].y);
        acc[r].z = fmaf(xv,wv.z,acc[r].z);
        acc[r].w = fmaf(xv,wv.w,acc[r].w);
      }
    }
  }
  #pragma unroll
  for (int r=0;r<8;++r)
    *(float4*)&g_k[(long)(r0blk + r0 + r)*DD + c0] = acc[r];
}

// ---------------- 8-warp block reduce ----------------
__device__ __forceinline__ float blkSum8(float v, float* red, int tid) {
  int lane = tid&31, w = tid>>5;
  #pragma unroll
  for (int o=16;o;o>>=1) v += __shfl_xor_sync(0xffffffffu,v,o);
  if (lane==0) red[w] = v;
  __syncthreads();
  float tot = red[0]+red[1]+red[2]+red[3]+red[4]+red[5]+red[6]+red[7];
  __syncthreads();
  return tot;
}

// ---------------- Q-phase: LN(slots) + Wq -> wa/wb/wc, 256 threads, 1 row ------
__device__ __forceinline__ void qphase(int r, const float* sv, float* sn,
                                       float* tmp, float* red,
                                       const float* __restrict__ lsg,
                                       const float* __restrict__ lsb, int t) {
  float x = sv[t];
  float m = blkSum8(x, red, t) * (1.f/256.f);
  float dv = x - m;
  float var = blkSum8(dv*dv, red, t) * (1.f/256.f);
  float rs = rsqrtf(var + 1e-5f);
  sn[t] = dv*rs*lsg[t] + lsb[t];
  __syncthreads();
  int idx = t & 127;
  const float* s = (t < 128) ? &sn[0] : &sn[128];
  float acc = 0.f;
  #pragma unroll 8
  for (int c=0;c<128;++c) acc = fmaf(s[c], g_WqT[c*DD+idx], acc);
  if (t >= 128) {
    float inv = expf(-2.f*acc);
    g_wa[r*DD+idx] = inv;
    tmp[idx] = inv;
  }
  __syncthreads();
  float cpart = 0.f;
  if (t < 128) {
    float inv = tmp[t];
    g_wb[r*DD+t] = -2.f*inv*acc;     // acc == qmu here
    g_mus[r*DD+t] = sn[t];
    g_accV[r*DD+t] = 0.f;
    g_accV2[r*DD+t] = 0.f;
    cpart = inv*acc*acc;
  }
  float C = blkSum8(cpart, red, t);
  if (t==0) { g_wc[r] = C; g_gsum[r] = 0.f; }
}

// ---------------- kInit: slot init + pi + first Q-phase ----------------
__global__ void kInit(const float* __restrict__ noise, const float* __restrict__ smu,
                      const float* __restrict__ slsig,
                      const float* __restrict__ lsg, const float* __restrict__ lsb) {
  __shared__ float sv[256];
  __shared__ float sn[256];
  __shared__ float tmp[128];
  __shared__ float red[8];
  int r = blockIdx.x, t = threadIdx.x;
  sv[t] = smu[t] + expf(slsig[t])*noise[r*256+t];
  if (t==0) g_pi[r] = 1.f/(float)NSL;
  __syncthreads();
  qphase(r, sv, sn, tmp, red, lsg, lsb, t);
}

// ---------------- kP: fused dots/gamma/moment pass (shuffle-free) --------------
// grid (16 b, 32 chunks of 64 n), 256 threads; 46.4 KB static smem
__global__ void __launch_bounds__(256, 4) kP() {
  __shared__ float4 ks4[CH*KSTR];          // 33792 B
  __shared__ float4 wa4[8*KSTR];           // 4224 B
  __shared__ float4 wb4[8*KSTR];           // 4224 B
  __shared__ float pd[8*64];               // 2048 B  [s][n] partial dots
  __shared__ float gm[CH*8];               // 2048 B  [n][s]
  __shared__ float sC[8], sPi[8];
  int b = blockIdx.x, chunk = blockIdx.y;
  int tid = threadIdx.x, lane = tid&31, w = tid>>5;
  { // stage wa/wb: 8 slots x 32 float4
    int s = tid>>5, i = tid&31;
    wa4[s*KSTR+i] = ((const float4*)&g_wa[(b*8+s)*DD])[i];
    wb4[s*KSTR+i] = ((const float4*)&g_wb[(b*8+s)*DD])[i];
  }
  if (tid<8) { sC[tid] = g_wc[b*8+tid]; sPi[tid] = g_pi[b*8+tid]; }
  for (int i=tid; i<512; i+=256) pd[i] = 0.f;
  { // stage k tile: 64 rows x 32 float4, coalesced
    const float4* src = (const float4*)&g_k[(long)b*NN*DD + (long)chunk*CH*DD];
    #pragma unroll
    for (int rep=0; rep<8; ++rep) {
      int i = rep*256 + tid;
      ks4[(i>>5)*KSTR + (i&31)] = src[i];
    }
  }
  __syncthreads();
  // phase 1: thread = (n = tid&63, dq = tid>>6); 8 slot partials over 32 d
  {
    int n = tid&63, dq = tid>>6;
    float acc[8];
    #pragma unroll
    for (int s=0;s<8;++s) acc[s]=0.f;
    const float4* kr = &ks4[n*KSTR + dq*8];
    #pragma unroll
    for (int i=0;i<8;++i) {
      float4 k4 = kr[i];
      #pragma unroll
      for (int s=0;s<8;++s) {
        float4 a4 = wa4[s*KSTR + dq*8 + i];
        float4 b4 = wb4[s*KSTR + dq*8 + i];
        float p = fmaf(a4.x,k4.x,b4.x)*k4.x;
        p = fmaf(fmaf(a4.y,k4.y,b4.y), k4.y, p);
        p = fmaf(fmaf(a4.z,k4.z,b4.z), k4.z, p);
        p = fmaf(fmaf(a4.w,k4.w,b4.w), k4.w, p);
        acc[s] += p;
      }
    }
    #pragma unroll
    for (int s=0;s<8;++s) atomicAdd(&pd[s*64+n], acc[s]);
  }
  __syncthreads();
  // phase 1b: threads 0..63 (n) do exp + softmax over 8 slots
  if (tid < 64) {
    int n = tid;
    float e[8], ssum = 0.f;
    #pragma unroll
    for (int s=0;s<8;++s) {
      float dot = pd[s*64+n] + sC[s];
      e[s] = (expf(-dot) + EPSV) * sPi[s];
      ssum += e[s];
    }
    float inv = 1.f/ssum;
    #pragma unroll
    for (int s=0;s<8;++s) gm[n*8+s] = e[s]*inv;
  }
  __syncthreads();
  // phase 2: warp = slot, lane = d4; accumulate moments + gsum
  {
    int s = w;
    float4 aV = make_float4(0,0,0,0), a2 = make_float4(0,0,0,0);
    float gsum = 0.f;
    #pragma unroll 4
    for (int n=0;n<CH;++n) {
      float g = gm[n*8+s];
      float4 k4 = ks4[n*KSTR+lane];
      gsum += g;
      aV.x = fmaf(g,k4.x,aV.x); aV.y = fmaf(g,k4.y,aV.y);
      aV.z = fmaf(g,k4.z,aV.z); aV.w = fmaf(g,k4.w,aV.w);
      a2.x = fmaf(g, k4.x*k4.x, a2.x); a2.y = fmaf(g, k4.y*k4.y, a2.y);
      a2.z = fmaf(g, k4.z*k4.z, a2.z); a2.w = fmaf(g, k4.w*k4.w, a2.w);
    }
    float* pV = &g_accV [(b*8+s)*DD + lane*4];
    float* p2 = &g_accV2[(b*8+s)*DD + lane*4];
    atomicAdd(pV+0,aV.x); atomicAdd(pV+1,aV.y);
    atomicAdd(pV+2,aV.z); atomicAdd(pV+3,aV.w);
    atomicAdd(p2+0,a2.x); atomicAdd(p2+1,a2.y);
    atomicAdd(p2+2,a2.z); atomicAdd(p2+3,a2.w);
    if (lane==0) atomicAdd(&g_gsum[b*8+s], gsum);
  }
}

// ---------------- kUQ: GRU + LN + MLP + logsigma, then Q-phase (or final MLP) ----
// 128 blocks (slot rows), 256 threads; GRU weights staged through smem (~36 KB)
__global__ void kUQ(const float* __restrict__ bih, const float* __restrict__ bhh,
                    const float* __restrict__ b1, const float* __restrict__ b2,
                    const float* __restrict__ lmg, const float* __restrict__ lmb,
                    const float* __restrict__ lsg, const float* __restrict__ lsb,
                    const float* __restrict__ b1o, const float* __restrict__ b2o,
                    float* __restrict__ outp, int last) {
  __shared__ float swih[8*384];            // 12 KB weight stage
  __shared__ float swhh[8*384];            // 12 KB
  __shared__ float s1s[128], s2s[128], mus[128];
  __shared__ float ps[6*256];
  __shared__ float hs[128];
  __shared__ float m1[128];
  __shared__ float sv[256];
  __shared__ float sn[256];
  __shared__ float tmp[128];
  __shared__ float red[8];
  int r = blockIdx.x, t = threadIdx.x, tt = t & 127, th = t >> 7;
  float gsum = g_gsum[r];
  if (t < 128) {
    float inv = 1.f/gsum;
    s1s[t] = g_accV[r*DD+t]*inv;
    s2s[t] = g_accV2[r*DD+t]*inv;
    mus[t] = g_mus[r*DD+t];
  }
  __syncthreads();
  // GRU gates: stage 8 c-rows of WihT/WhhT per chunk (16 chunks), 4 c per thread
  {
    float gir=0,giz=0,gin=0,ghr=0,ghz=0,ghn=0;
    for (int ch=0; ch<16; ++ch) {
      __syncthreads();
      const float4* si = (const float4*)&g_WihT[ch*8*384];
      const float4* sh = (const float4*)&g_WhhT[ch*8*384];
      #pragma unroll
      for (int rep=0; rep<3; ++rep) {
        int i = rep*256 + t;   // 8*96 = 768 float4
        ((float4*)swih)[i] = si[i];
        ((float4*)swhh)[i] = sh[i];
      }
      __syncthreads();
      int cl0 = th*4;
      #pragma unroll
      for (int ci=0; ci<4; ++ci) {
        int cl = cl0 + ci, c = ch*8 + cl;
        float xv = s1s[c], hv = mus[c];
        const float* wi = &swih[cl*384];
        const float* wh = &swhh[cl*384];
        gir = fmaf(xv, wi[tt],     gir);  ghr = fmaf(hv, wh[tt],     ghr);
        giz = fmaf(xv, wi[128+tt], giz);  ghz = fmaf(hv, wh[128+tt], ghz);
        gin = fmaf(xv, wi[256+tt], gin);  ghn = fmaf(hv, wh[256+tt], ghn);
      }
    }
    ps[t]=gir; ps[256+t]=giz; ps[512+t]=gin;
    ps[768+t]=ghr; ps[1024+t]=ghz; ps[1280+t]=ghn;
  }
  __syncthreads();
  float upd1 = 0.f;
  if (t < 128) {
    float Gir = ps[t]+ps[t+128]       + bih[t];
    float Giz = ps[256+t]+ps[384+t]   + bih[128+t];
    float Gin = ps[512+t]+ps[640+t]   + bih[256+t];
    float Ghr = ps[768+t]+ps[896+t]   + bhh[t];
    float Ghz = ps[1024+t]+ps[1152+t] + bhh[128+t];
    float Ghn = ps[1280+t]+ps[1408+t] + bhh[256+t];
    float rg = 1.f/(1.f+expf(-(Gir+Ghr)));
    float zg = 1.f/(1.f+expf(-(Giz+Ghz)));
    float ng = tanhf(Gin + rg*Ghn);
    upd1 = (1.f-zg)*ng + zg*mus[t];
  }
  __syncthreads();
  // LN(upd1) over 128 (inactive threads contribute 0)
  {
    float v = (t<128) ? upd1 : 0.f;
    float m = blkSum8(v, red, t) * (1.f/128.f);
    float dv = (t<128) ? (upd1 - m) : 0.f;
    float var = blkSum8(dv*dv, red, t) * (1.f/128.f);
    float rs = rsqrtf(var + 1e-5f);
    if (t<128) hs[t] = dv*rs*lmg[t] + lmb[t];
  }
  __syncthreads();
  // MLP1: split c over halves
  {
    float a = 0.f;
    int c0 = th*64;
    #pragma unroll 8
    for (int c=c0; c<c0+64; ++c) a = fmaf(hs[c], g_W1muT[c*HH+tt], a);
    ps[t] = a;
  }
  __syncthreads();
  if (t < 128) m1[t] = fmaxf(ps[t]+ps[t+128]+b1[t], 0.f);
  __syncthreads();
  // MLP2: split j over halves
  {
    float a = 0.f;
    int j0 = th*64;
    #pragma unroll 8
    for (int j=j0; j<j0+64; ++j) a = fmaf(m1[j], g_W2muT[j*DD+tt], a);
    ps[t] = a;
  }
  __syncthreads();
  if (t < 128) {
    float out = upd1 + b2[t] + ps[t] + ps[t+128];
    float ls = 0.5f*logf(s2s[t] - 2.f*out*s1s[t] + out*out + EPSV);
    sv[t] = out;
    sv[128+t] = ls;
    if (t==0) g_pi[r] = gsum;
  }
  __syncthreads();
  if (!last) {
    qphase(r, sv, sn, tmp, red, lsg, lsb, t);
  } else {
    // final output MLP: h = relu(sv @ W1o^T + b1o), out = h @ W2o^T + b2o
    float a = b1o[t];
    #pragma unroll 8
    for (int c=0;c<256;++c) a = fmaf(sv[c], g_W1oT[c*256+t], a);
    sn[t] = fmaxf(a, 0.f);
    __syncthreads();
    if (t < 128) {
      float o = b2o[t];
      #pragma unroll 8
      for (int c=0;c<256;++c) o = fmaf(sn[c], g_W2oT[c*DD+t], o);
      outp[r*DD+t] = o;
    }
  }
}

extern "C" void kernel_launch(void* const* d_in, const int* in_sizes, int n_in,
                              void* d_out, int out_size) {
  const float* inputs  = (const float*)d_in[0];
  const float* noise   = (const float*)d_in[1];
  const float* smu     = (const float*)d_in[2];
  const float* slsig   = (const float*)d_in[3];
  const float* Wq      = (const float*)d_in[4];
  const float* Wk      = (const float*)d_in[5];
  const float* Wih     = (const float*)d_in[6];
  const float* Whh     = (const float*)d_in[7];
  const float* bih     = (const float*)d_in[8];
  const float* bhh     = (const float*)d_in[9];
  const float* W1mu    = (const float*)d_in[10];
  const float* b1mu    = (const float*)d_in[11];
  const float* W2mu    = (const float*)d_in[12];
  const float* b2mu    = (const float*)d_in[13];
  const float* ln_in_g = (const float*)d_in[14];
  const float* ln_in_b = (const float*)d_in[15];
  const float* lsg     = (const float*)d_in[16];
  const float* lsb     = (const float*)d_in[17];
  const float* lmg     = (const float*)d_in[18];
  const float* lmb     = (const float*)d_in[19];
  const float* W1o     = (const float*)d_in[20];
  const float* b1o     = (const float*)d_in[21];
  const float* W2o     = (const float*)d_in[22];
  const float* b2o     = (const float*)d_in[23];
  float* out = (float*)d_out;

  kT<<<64, 256>>>(Wk, Wq, Wih, Whh, W1mu, W2mu, W1o, W2o);
  kA<<<(BB*NN)/64, 256>>>(inputs, ln_in_g, ln_in_b);
  kInit<<<RWS, 256>>>(noise, smu, slsig, lsg, lsb);
  for (int it=0; it<4; ++it) {
    kP<<<dim3(BB, NN/CH), 256>>>();
    kUQ<<<RWS, 256>>>(bih, bhh, b1mu, b2mu, lmg, lmb, lsg, lsb,
                      b1o, b2o, out, it==3 ? 1 : 0);
  }
}

// round 8
// speedup vs baseline: 1.4399x; 1.2000x over previous
#include <cuda_runtime.h>
#include <math.h>

#define BB   16
#define NN   2048
#define DD   128
#define NSL  8
#define HH   128
#define RWS  (BB*NSL)            // 128 slot rows
#define EPSV 1e-8f
#define CH   64                  // n-rows per kP chunk
#define KSTR 33                  // float4 stride for ks rows

// ---------------- scratch (__device__ globals: allocation-free) ----------------
__device__ float g_k[BB*NN*DD];          // 16 MB, k == v
__device__ float g_mus[RWS*DD];          // mu_s (GRU hidden)
__device__ float g_wa[RWS*DD];           // inv_var
__device__ float g_wb[RWS*DD];           // -2*inv*qmu
__device__ float g_wc[RWS];              // sum inv*qmu^2
__device__ float g_pi[RWS];
__device__ float g_gsum[RWS];
__device__ float g_accV[RWS*DD];
__device__ float g_accV2[RWS*DD];

// transposed weights
__device__ float g_WkT[DD*DD];           // [kk][c]
__device__ float g_WqT[DD*DD];           // [c][d]
__device__ float g_WihT[DD*3*DD];        // [c][j]
__device__ float g_WhhT[DD*3*DD];
__device__ float g_W1muT[DD*HH];         // [c][j]
__device__ float g_W2muT[HH*DD];         // [j][d]
__device__ float g_W1oT[2*DD*2*HH];      // [c][j]
__device__ float g_W2oT[2*HH*DD];        // [c][d]

// ---------------- kNop: shifts ncu's -s 5 window onto kUQ ----------------
__global__ void kNop() {}

// ---------------- kT: one-time weight transposes ----------------
__global__ void kT(const float* __restrict__ Wk, const float* __restrict__ Wq,
                   const float* __restrict__ Wih, const float* __restrict__ Whh,
                   const float* __restrict__ W1mu, const float* __restrict__ W2mu,
                   const float* __restrict__ W1o, const float* __restrict__ W2o) {
  int tid = blockIdx.x*blockDim.x + threadIdx.x;
  int stride = gridDim.x*blockDim.x;
  for (int i=tid;i<DD*DD;i+=stride){int c=i>>7,kk=i&127; g_WkT[kk*DD+c]=Wk[i];}
  for (int i=tid;i<DD*DD;i+=stride){int d=i>>7,c=i&127;  g_WqT[c*DD+d]=Wq[i];}
  for (int i=tid;i<3*DD*DD;i+=stride){int j=i>>7,c=i&127; g_WihT[c*384+j]=Wih[i]; g_WhhT[c*384+j]=Whh[i];}
  for (int i=tid;i<HH*DD;i+=stride){int j=i>>7,c=i&127;  g_W1muT[c*HH+j]=W1mu[i];}
  for (int i=tid;i<DD*HH;i+=stride){int d=i>>7,j=i&127;  g_W2muT[j*DD+d]=W2mu[i];}
  for (int i=tid;i<2*HH*2*DD;i+=stride){int j=i>>8,c=i&255; g_W1oT[c*256+j]=W1o[i];}
  for (int i=tid;i<DD*2*HH;i+=stride){int d=i>>8,c=i&255; g_W2oT[c*DD+d]=W2o[i];}
}

// ---------------- kA: fused LayerNorm + k = xn @ Wk^T ----------------
__global__ void kA(const float* __restrict__ inp,
                   const float* __restrict__ lng, const float* __restrict__ lnb) {
  __shared__ float xs[64*DD];
  __shared__ float wt[16*DD];
  const int tid = threadIdx.x;
  const int r0blk = blockIdx.x*64;
  for (int idx=tid; idx<64*DD; idx+=256) xs[idx] = inp[(long)r0blk*DD + idx];
  __syncthreads();
  { // LayerNorm: warp w -> rows w*8..w*8+7
    int w = tid>>5, lane = tid&31;
    for (int r=w*8; r<w*8+8; ++r) {
      float x0=xs[r*DD+lane],    x1=xs[r*DD+lane+32];
      float x2=xs[r*DD+lane+64], x3=xs[r*DD+lane+96];
      float s = x0+x1+x2+x3;
      #pragma unroll
      for (int o=16;o;o>>=1) s += __shfl_xor_sync(0xffffffffu,s,o);
      float m = s*(1.f/128.f);
      float d0=x0-m,d1=x1-m,d2=x2-m,d3=x3-m;
      float s2 = d0*d0+d1*d1+d2*d2+d3*d3;
      #pragma unroll
      for (int o=16;o;o>>=1) s2 += __shfl_xor_sync(0xffffffffu,s2,o);
      float rs = rsqrtf(s2*(1.f/128.f)+1e-5f);
      xs[r*DD+lane]    = d0*rs*lng[lane]    + lnb[lane];
      xs[r*DD+lane+32] = d1*rs*lng[lane+32] + lnb[lane+32];
      xs[r*DD+lane+64] = d2*rs*lng[lane+64] + lnb[lane+64];
      xs[r*DD+lane+96] = d3*rs*lng[lane+96] + lnb[lane+96];
    }
  }
  const int cg = tid&31, rg = tid>>5;
  const int c0 = cg*4, r0 = rg*8;
  float4 acc[8];
  #pragma unroll
  for (int r=0;r<8;++r) acc[r] = make_float4(0.f,0.f,0.f,0.f);
  for (int kt=0; kt<8; ++kt) {
    __syncthreads();
    for (int i=tid; i<16*DD; i+=256) wt[i] = g_WkT[kt*16*DD + i];
    __syncthreads();
    #pragma unroll 4
    for (int kk=0;kk<16;++kk) {
      float4 wv = *(const float4*)&wt[kk*DD+c0];
      int kg = kt*16 + kk;
      #pragma unroll
      for (int r=0;r<8;++r) {
        float xv = xs[(r0+r)*DD+kg];
        acc[r].x = fmaf(xv,wv.x,acc[r].x);
        acc[r].y = fmaf(xv,wv.y,acc[r].y);
        acc[r].z = fmaf(xv,wv.z,acc[r].z);
        acc[r].w = fmaf(xv,wv.w,acc[r].w);
      }
    }
  }
  #pragma unroll
  for (int r=0;r<8;++r)
    *(float4*)&g_k[(long)(r0blk + r0 + r)*DD + c0] = acc[r];
}

// ---------------- 8-warp block reduce ----------------
__device__ __forceinline__ float blkSum8(float v, float* red, int tid) {
  int lane = tid&31, w = tid>>5;
  #pragma unroll
  for (int o=16;o;o>>=1) v += __shfl_xor_sync(0xffffffffu,v,o);
  if (lane==0) red[w] = v;
  __syncthreads();
  float tot = red[0]+red[1]+red[2]+red[3]+red[4]+red[5]+red[6]+red[7];
  __syncthreads();
  return tot;
}

// ---------------- Q-phase: LN(slots) + Wq -> wa/wb/wc, 256 threads, 1 row ------
__device__ __forceinline__ void qphase(int r, const float* sv, float* sn,
                                       float* tmp, float* red,
                                       const float* __restrict__ lsg,
                                       const float* __restrict__ lsb, int t) {
  float x = sv[t];
  float m = blkSum8(x, red, t) * (1.f/256.f);
  float dv = x - m;
  float var = blkSum8(dv*dv, red, t) * (1.f/256.f);
  float rs = rsqrtf(var + 1e-5f);
  sn[t] = dv*rs*lsg[t] + lsb[t];
  __syncthreads();
  int idx = t & 127;
  const float* s = (t < 128) ? &sn[0] : &sn[128];
  float acc = 0.f;
  #pragma unroll 16
  for (int c=0;c<128;++c) acc = fmaf(s[c], g_WqT[c*DD+idx], acc);
  if (t >= 128) {
    float inv = expf(-2.f*acc);
    g_wa[r*DD+idx] = inv;
    tmp[idx] = inv;
  }
  __syncthreads();
  float cpart = 0.f;
  if (t < 128) {
    float inv = tmp[t];
    g_wb[r*DD+t] = -2.f*inv*acc;     // acc == qmu here
    g_mus[r*DD+t] = sn[t];
    g_accV[r*DD+t] = 0.f;
    g_accV2[r*DD+t] = 0.f;
    cpart = inv*acc*acc;
  }
  float C = blkSum8(cpart, red, t);
  if (t==0) { g_wc[r] = C; g_gsum[r] = 0.f; }
}

// ---------------- kInit: slot init + pi + first Q-phase ----------------
__global__ void kInit(const float* __restrict__ noise, const float* __restrict__ smu,
                      const float* __restrict__ slsig,
                      const float* __restrict__ lsg, const float* __restrict__ lsb) {
  __shared__ float sv[256];
  __shared__ float sn[256];
  __shared__ float tmp[128];
  __shared__ float red[8];
  int r = blockIdx.x, t = threadIdx.x;
  sv[t] = smu[t] + expf(slsig[t])*noise[r*256+t];
  if (t==0) g_pi[r] = 1.f/(float)NSL;
  __syncthreads();
  qphase(r, sv, sn, tmp, red, lsg, lsb, t);
}

// ---------------- kP: fused dots/gamma/moment pass (shuffle-free) --------------
// grid (16 b, 32 chunks of 64 n), 256 threads; 46.4 KB static smem
__global__ void __launch_bounds__(256, 4) kP() {
  __shared__ float4 ks4[CH*KSTR];          // 33792 B
  __shared__ float4 wa4[8*KSTR];           // 4224 B
  __shared__ float4 wb4[8*KSTR];           // 4224 B
  __shared__ float pd[8*64];               // 2048 B  [s][n] partial dots
  __shared__ float gm[CH*8];               // 2048 B  [n][s]
  __shared__ float sC[8], sPi[8];
  int b = blockIdx.x, chunk = blockIdx.y;
  int tid = threadIdx.x, lane = tid&31, w = tid>>5;
  { // stage wa/wb: 8 slots x 32 float4
    int s = tid>>5, i = tid&31;
    wa4[s*KSTR+i] = ((const float4*)&g_wa[(b*8+s)*DD])[i];
    wb4[s*KSTR+i] = ((const float4*)&g_wb[(b*8+s)*DD])[i];
  }
  if (tid<8) { sC[tid] = g_wc[b*8+tid]; sPi[tid] = g_pi[b*8+tid]; }
  for (int i=tid; i<512; i+=256) pd[i] = 0.f;
  { // stage k tile: 64 rows x 32 float4, coalesced
    const float4* src = (const float4*)&g_k[(long)b*NN*DD + (long)chunk*CH*DD];
    #pragma unroll
    for (int rep=0; rep<8; ++rep) {
      int i = rep*256 + tid;
      ks4[(i>>5)*KSTR + (i&31)] = src[i];
    }
  }
  __syncthreads();
  // phase 1: thread = (n = tid&63, dq = tid>>6); 8 slot partials over 32 d
  {
    int n = tid&63, dq = tid>>6;
    float acc[8];
    #pragma unroll
    for (int s=0;s<8;++s) acc[s]=0.f;
    const float4* kr = &ks4[n*KSTR + dq*8];
    #pragma unroll
    for (int i=0;i<8;++i) {
      float4 k4 = kr[i];
      #pragma unroll
      for (int s=0;s<8;++s) {
        float4 a4 = wa4[s*KSTR + dq*8 + i];
        float4 b4 = wb4[s*KSTR + dq*8 + i];
        float p = fmaf(a4.x,k4.x,b4.x)*k4.x;
        p = fmaf(fmaf(a4.y,k4.y,b4.y), k4.y, p);
        p = fmaf(fmaf(a4.z,k4.z,b4.z), k4.z, p);
        p = fmaf(fmaf(a4.w,k4.w,b4.w), k4.w, p);
        acc[s] += p;
      }
    }
    #pragma unroll
    for (int s=0;s<8;++s) atomicAdd(&pd[s*64+n], acc[s]);
  }
  __syncthreads();
  // phase 1b: threads 0..63 (n) do exp + softmax over 8 slots
  if (tid < 64) {
    int n = tid;
    float e[8], ssum = 0.f;
    #pragma unroll
    for (int s=0;s<8;++s) {
      float dot = pd[s*64+n] + sC[s];
      e[s] = (expf(-dot) + EPSV) * sPi[s];
      ssum += e[s];
    }
    float inv = 1.f/ssum;
    #pragma unroll
    for (int s=0;s<8;++s) gm[n*8+s] = e[s]*inv;
  }
  __syncthreads();
  // phase 2: warp = (slot-pair sp = w&3, n-half nh = w>>2); lane = d4
  {
    int sp = w & 3, nh = w >> 2;
    int s0 = sp*2, s1 = sp*2+1;
    float4 aV0 = make_float4(0,0,0,0), a20 = make_float4(0,0,0,0);
    float4 aV1 = make_float4(0,0,0,0), a21 = make_float4(0,0,0,0);
    float gs0 = 0.f, gs1 = 0.f;
    #pragma unroll 4
    for (int ni=0; ni<32; ++ni) {
      int n = nh*32 + ni;
      float4 k4 = ks4[n*KSTR+lane];
      float2 g2 = *(const float2*)&gm[n*8 + s0];
      float g0 = g2.x, g1 = g2.y;
      gs0 += g0; gs1 += g1;
      float sx = k4.x*k4.x, sy = k4.y*k4.y, sz = k4.z*k4.z, sw = k4.w*k4.w;
      aV0.x = fmaf(g0,k4.x,aV0.x); aV0.y = fmaf(g0,k4.y,aV0.y);
      aV0.z = fmaf(g0,k4.z,aV0.z); aV0.w = fmaf(g0,k4.w,aV0.w);
      a20.x = fmaf(g0,sx,a20.x); a20.y = fmaf(g0,sy,a20.y);
      a20.z = fmaf(g0,sz,a20.z); a20.w = fmaf(g0,sw,a20.w);
      aV1.x = fmaf(g1,k4.x,aV1.x); aV1.y = fmaf(g1,k4.y,aV1.y);
      aV1.z = fmaf(g1,k4.z,aV1.z); aV1.w = fmaf(g1,k4.w,aV1.w);
      a21.x = fmaf(g1,sx,a21.x); a21.y = fmaf(g1,sy,a21.y);
      a21.z = fmaf(g1,sz,a21.z); a21.w = fmaf(g1,sw,a21.w);
    }
    float* pV0 = &g_accV [(b*8+s0)*DD + lane*4];
    float* p20 = &g_accV2[(b*8+s0)*DD + lane*4];
    float* pV1 = &g_accV [(b*8+s1)*DD + lane*4];
    float* p21 = &g_accV2[(b*8+s1)*DD + lane*4];
    atomicAdd(pV0+0,aV0.x); atomicAdd(pV0+1,aV0.y);
    atomicAdd(pV0+2,aV0.z); atomicAdd(pV0+3,aV0.w);
    atomicAdd(p20+0,a20.x); atomicAdd(p20+1,a20.y);
    atomicAdd(p20+2,a20.z); atomicAdd(p20+3,a20.w);
    atomicAdd(pV1+0,aV1.x); atomicAdd(pV1+1,aV1.y);
    atomicAdd(pV1+2,aV1.z); atomicAdd(pV1+3,aV1.w);
    atomicAdd(p21+0,a21.x); atomicAdd(p21+1,a21.y);
    atomicAdd(p21+2,a21.z); atomicAdd(p21+3,a21.w);
    if (lane==0) { atomicAdd(&g_gsum[b*8+s0], gs0); atomicAdd(&g_gsum[b*8+s1], gs1); }
  }
}

// ---------------- kUQ: GRU + LN + MLP + logsigma, then Q-phase (or final MLP) ----
// 128 blocks (slot rows), 256 threads; GRU weights reg-double-buffered via smem
__global__ void kUQ(const float* __restrict__ bih, const float* __restrict__ bhh,
                    const float* __restrict__ b1, const float* __restrict__ b2,
                    const float* __restrict__ lmg, const float* __restrict__ lmb,
                    const float* __restrict__ lsg, const float* __restrict__ lsb,
                    const float* __restrict__ b1o, const float* __restrict__ b2o,
                    float* __restrict__ outp, int last) {
  __shared__ float swih[8*384];            // 12 KB weight stage
  __shared__ float swhh[8*384];            // 12 KB
  __shared__ float s1s[128], s2s[128], mus[128];
  __shared__ float ps[6*256];
  __shared__ float hs[128];
  __shared__ float m1[128];
  __shared__ float sv[256];
  __shared__ float sn[256];
  __shared__ float tmp[128];
  __shared__ float red[8];
  int r = blockIdx.x, t = threadIdx.x, tt = t & 127, th = t >> 7;
  float gsum = g_gsum[r];
  if (t < 128) {
    float inv = 1.f/gsum;
    s1s[t] = g_accV[r*DD+t]*inv;
    s2s[t] = g_accV2[r*DD+t]*inv;
    mus[t] = g_mus[r*DD+t];
  }
  __syncthreads();
  // GRU gates: 16 chunks of 8 c-rows, register double-buffered staging
  {
    const float4* giT = (const float4*)g_WihT;
    const float4* ghT = (const float4*)g_WhhT;
    float4 ri[3], rh[3];
    #pragma unroll
    for (int rep=0;rep<3;++rep) { ri[rep]=giT[rep*256+t]; rh[rep]=ghT[rep*256+t]; }
    float gir=0,giz=0,gin=0,ghr=0,ghz=0,ghn=0;
    for (int ch=0; ch<16; ++ch) {
      __syncthreads();
      #pragma unroll
      for (int rep=0;rep<3;++rep) {
        ((float4*)swih)[rep*256+t]=ri[rep];
        ((float4*)swhh)[rep*256+t]=rh[rep];
      }
      __syncthreads();
      if (ch<15) {
        #pragma unroll
        for (int rep=0;rep<3;++rep) {
          ri[rep]=giT[(ch+1)*768+rep*256+t];
          rh[rep]=ghT[(ch+1)*768+rep*256+t];
        }
      }
      int cl0 = th*4;
      #pragma unroll
      for (int ci=0; ci<4; ++ci) {
        int cl = cl0 + ci, c = ch*8 + cl;
        float xv = s1s[c], hv = mus[c];
        const float* wi = &swih[cl*384];
        const float* wh = &swhh[cl*384];
        gir = fmaf(xv, wi[tt],     gir);  ghr = fmaf(hv, wh[tt],     ghr);
        giz = fmaf(xv, wi[128+tt], giz);  ghz = fmaf(hv, wh[128+tt], ghz);
        gin = fmaf(xv, wi[256+tt], gin);  ghn = fmaf(hv, wh[256+tt], ghn);
      }
    }
    ps[t]=gir; ps[256+t]=giz; ps[512+t]=gin;
    ps[768+t]=ghr; ps[1024+t]=ghz; ps[1280+t]=ghn;
  }
  __syncthreads();
  float upd1 = 0.f;
  if (t < 128) {
    float Gir = ps[t]+ps[t+128]       + bih[t];
    float Giz = ps[256+t]+ps[384+t]   + bih[128+t];
    float Gin = ps[512+t]+ps[640+t]   + bih[256+t];
    float Ghr = ps[768+t]+ps[896+t]   + bhh[t];
    float Ghz = ps[1024+t]+ps[1152+t] + bhh[128+t];
    float Ghn = ps[1280+t]+ps[1408+t] + bhh[256+t];
    float rg = 1.f/(1.f+expf(-(Gir+Ghr)));
    float zg = 1.f/(1.f+expf(-(Giz+Ghz)));
    float ng = tanhf(Gin + rg*Ghn);
    upd1 = (1.f-zg)*ng + zg*mus[t];
  }
  __syncthreads();
  // LN(upd1) over 128 (inactive threads contribute 0)
  {
    float v = (t<128) ? upd1 : 0.f;
    float m = blkSum8(v, red, t) * (1.f/128.f);
    float dv = (t<128) ? (upd1 - m) : 0.f;
    float var = blkSum8(dv*dv, red, t) * (1.f/128.f);
    float rs = rsqrtf(var + 1e-5f);
    if (t<128) hs[t] = dv*rs*lmg[t] + lmb[t];
  }
  __syncthreads();
  // MLP1: split c over halves
  {
    float a = 0.f;
    int c0 = th*64;
    #pragma unroll 16
    for (int c=c0; c<c0+64; ++c) a = fmaf(hs[c], g_W1muT[c*HH+tt], a);
    ps[t] = a;
  }
  __syncthreads();
  if (t < 128) m1[t] = fmaxf(ps[t]+ps[t+128]+b1[t], 0.f);
  __syncthreads();
  // MLP2: split j over halves
  {
    float a = 0.f;
    int j0 = th*64;
    #pragma unroll 16
    for (int j=j0; j<j0+64; ++j) a = fmaf(m1[j], g_W2muT[j*DD+tt], a);
    ps[t] = a;
  }
  __syncthreads();
  if (t < 128) {
    float out = upd1 + b2[t] + ps[t] + ps[t+128];
    float ls = 0.5f*logf(s2s[t] - 2.f*out*s1s[t] + out*out + EPSV);
    sv[t] = out;
    sv[128+t] = ls;
    if (t==0) g_pi[r] = gsum;
  }
  __syncthreads();
  if (!last) {
    qphase(r, sv, sn, tmp, red, lsg, lsb, t);
  } else {
    // final output MLP: h = relu(sv @ W1o^T + b1o), out = h @ W2o^T + b2o
    float a = b1o[t];
    #pragma unroll 16
    for (int c=0;c<256;++c) a = fmaf(sv[c], g_W1oT[c*256+t], a);
    sn[t] = fmaxf(a, 0.f);
    __syncthreads();
    if (t < 128) {
      float o = b2o[t];
      #pragma unroll 16
      for (int c=0;c<256;++c) o = fmaf(sn[c], g_W2oT[c*DD+t], o);
      outp[r*DD+t] = o;
    }
  }
}

extern "C" void kernel_launch(void* const* d_in, const int* in_sizes, int n_in,
                              void* d_out, int out_size) {
  const float* inputs  = (const float*)d_in[0];
  const float* noise   = (const float*)d_in[1];
  const float* smu     = (const float*)d_in[2];
  const float* slsig   = (const float*)d_in[3];
  const float* Wq      = (const float*)d_in[4];
  const float* Wk      = (const float*)d_in[5];
  const float* Wih     = (const float*)d_in[6];
  const float* Whh     = (const float*)d_in[7];
  const float* bih     = (const float*)d_in[8];
  const float* bhh     = (const float*)d_in[9];
  const float* W1mu    = (const float*)d_in[10];
  const float* b1mu    = (const float*)d_in[11];
  const float* W2mu    = (const float*)d_in[12];
  const float* b2mu    = (const float*)d_in[13];
  const float* ln_in_g = (const float*)d_in[14];
  const float* ln_in_b = (const float*)d_in[15];
  const float* lsg     = (const float*)d_in[16];
  const float* lsb     = (const float*)d_in[17];
  const float* lmg     = (const float*)d_in[18];
  const float* lmb     = (const float*)d_in[19];
  const float* W1o     = (const float*)d_in[20];
  const float* b1o     = (const float*)d_in[21];
  const float* W2o     = (const float*)d_in[22];
  const float* b2o     = (const float*)d_in[23];
  float* out = (float*)d_out;

  kNop<<<1, 32>>>();
  kT<<<64, 256>>>(Wk, Wq, Wih, Whh, W1mu, W2mu, W1o, W2o);
  kA<<<(BB*NN)/64, 256>>>(inputs, ln_in_g, ln_in_b);
  kInit<<<RWS, 256>>>(noise, smu, slsig, lsg, lsb);
  for (int it=0; it<4; ++it) {
    kP<<<dim3(BB, NN/CH), 256>>>();
    kUQ<<<RWS, 256>>>(bih, bhh, b1mu, b2mu, lmg, lmb, lsg, lsb,
                      b1o, b2o, out, it==3 ? 1 : 0);
  }
}